// round 7
// baseline (speedup 1.0000x reference)
#include <cuda_runtime.h>
#include <cuda_fp16.h>

// ---------------- scratch (device globals; no allocation allowed) ----------
#define NMAX  100032
#define ECAP  1664000

__device__ __half g_h [NMAX * 64];   // GEMM output (pre-scaled by dis[row]), fp16
__device__ __half g_a [NMAX * 64];   // post-aggregation activations, fp16
__device__ float  g_dis[NMAX];
__device__ int    g_cnt[NMAX];
__device__ int    g_rptr[NMAX];      // after fill: block-local inclusive prefix
__device__ int    g_col[ECAP];
__device__ int    g_bsum[128];       // exclusive scan of block totals (carry)

// ---------------- preprocessing kernels ------------------------------------

__global__ void k_hist(const int* __restrict__ dst, int E) {
    int e = (blockIdx.x * 256 + threadIdx.x) * 4;
    if (e + 4 <= E) {
        int4 d = *(const int4*)(dst + e);
        atomicAdd(&g_cnt[d.x], 1);
        atomicAdd(&g_cnt[d.y], 1);
        atomicAdd(&g_cnt[d.z], 1);
        atomicAdd(&g_cnt[d.w], 1);
    } else {
        for (; e < E; e++) atomicAdd(&g_cnt[dst[e]], 1);
    }
}

// block-wide exclusive scan helper (blockDim.x == 1024)
__device__ __forceinline__ int blockscan_excl(int v, int* total) {
    __shared__ int ws[32];
    int lane = threadIdx.x & 31, wid = threadIdx.x >> 5;
    int s = v;
#pragma unroll
    for (int o = 1; o < 32; o <<= 1) {
        int t = __shfl_up_sync(0xffffffffu, s, o);
        if (lane >= o) s += t;
    }
    if (lane == 31) ws[wid] = s;
    __syncthreads();
    if (wid == 0) {
        int u = ws[lane];
#pragma unroll
        for (int o = 1; o < 32; o <<= 1) {
            int t = __shfl_up_sync(0xffffffffu, u, o);
            if (lane >= o) u += t;
        }
        ws[lane] = u;
    }
    __syncthreads();
    int incl = s + (wid ? ws[wid - 1] : 0);
    if (total) *total = ws[31];
    return incl - v;
}

// per-block exclusive scan of cnt -> rptr (local), block totals -> bsum,
// fused with dis = rsqrt(deg+1)
__global__ void k_scan1(int n) {
    int i = blockIdx.x * 1024 + threadIdx.x;
    int v = (i < n) ? g_cnt[i] : 0;
    int tot;
    int ex = blockscan_excl(v, &tot);
    if (i < n) {
        g_rptr[i] = ex;
        g_dis[i] = rsqrtf((float)(v + 1));   // +1 self loop; always > 0
    }
    if (threadIdx.x == 0) g_bsum[blockIdx.x] = tot;
}

// exclusive scan of block sums (single block)
__global__ void k_scan2(int nb) {
    int i = threadIdx.x;
    int v = (i < nb) ? g_bsum[i] : 0;   // reads complete before writes (barrier in scan)
    int ex = blockscan_excl(v, nullptr);
    if (i < nb) g_bsum[i] = ex;
}

// CSR fill. Slot = local post-increment + block carry.
__global__ void k_fill(const int* __restrict__ src, const int* __restrict__ dst, int E) {
    int e = (blockIdx.x * 256 + threadIdx.x) * 4;
    if (e + 4 <= E) {
        int4 d = *(const int4*)(dst + e);
        int4 s = *(const int4*)(src + e);
        g_col[atomicAdd(&g_rptr[d.x], 1) + g_bsum[d.x >> 10]] = s.x;
        g_col[atomicAdd(&g_rptr[d.y], 1) + g_bsum[d.y >> 10]] = s.y;
        g_col[atomicAdd(&g_rptr[d.z], 1) + g_bsum[d.z >> 10]] = s.z;
        g_col[atomicAdd(&g_rptr[d.w], 1) + g_bsum[d.w >> 10]] = s.w;
    } else {
        for (; e < E; e++) {
            int d = dst[e];
            g_col[atomicAdd(&g_rptr[d], 1) + g_bsum[d >> 10]] = src[e];
        }
    }
}

// ---------------- GEMM via mma.sync (HMMA), split-fp16 = fp32 accuracy ------
// H[n,64] = (A[n,K] @ W[K,64]) * dis[row]  -> fp16 g_h
// Block: 64 rows x 64 cols, 8 warps (wm = wid&3 row-tile, wn = wid>>2 col-half).
// Warp tile: 16 rows x 32 cols = 4 n-fragments of m16n8k16.
// !HALF_IN: A = fp32 x, split into hi+lo fp16 in smem; W split hi+lo:
//   D = Ah*Wh + Ah*Wl + Al*Wh   (dropped Al*Wl ~ eps^2 ~ 6e-8)
// HALF_IN:  A = g_a (exact fp16); D = A*Wh + A*Wl (numerically == fp32 gemm).
// W staged TRANSPOSED in smem (WT[n][k]) so B-fragment k-pairs are contiguous.
__device__ __forceinline__ void mma16816(float acc[4], const unsigned a[4],
                                         const unsigned b[2]) {
    asm volatile(
        "mma.sync.aligned.m16n8k16.row.col.f32.f16.f16.f32 "
        "{%0,%1,%2,%3}, {%4,%5,%6,%7}, {%8,%9}, {%0,%1,%2,%3};\n"
        : "+f"(acc[0]), "+f"(acc[1]), "+f"(acc[2]), "+f"(acc[3])
        : "r"(a[0]), "r"(a[1]), "r"(a[2]), "r"(a[3]), "r"(b[0]), "r"(b[1]));
}

template <int K, bool HALF_IN>
__global__ void __launch_bounds__(256) k_gemm_mma(const float* __restrict__ Ain,
                                                  const float* __restrict__ W, int n) {
    constexpr int LD = K + 8;        // halves per row (even; rows 4B-aligned)
    extern __shared__ __align__(16) char dyn[];
    __half* sWh = (__half*)dyn;              // [64][LD]  W^T hi
    __half* sWl = sWh + 64 * LD;             // [64][LD]  W^T lo
    __half* sAh = sWl + 64 * LD;             // [64][LD]  A hi (or exact A)
    __half* sAl = sAh + 64 * LD;             // [64][LD]  A lo (layer-1 only)

    int tid = threadIdx.x;
    int wid = tid >> 5, lane = tid & 31;
    int wm = wid & 3, wn = wid >> 2;
    int row0 = blockIdx.x * 64;

    // stage W transposed, hi/lo split
    for (int i = tid; i < K * 64; i += 256) {
        int k = i >> 6, nn = i & 63;
        float w = W[i];
        __half h = __float2half_rn(w);
        sWh[nn * LD + k] = h;
        sWl[nn * LD + k] = __float2half_rn(w - __half2float(h));
    }

    // stage A
    if (HALF_IN) {
        // exact fp16 copy from g_a (NMAX is a multiple of 64: no OOB reads)
        for (int i = tid; i < 64 * (K / 8); i += 256) {
            int row = i / (K / 8), c8 = i % (K / 8);
            uint4 v = *(const uint4*)(g_a + (size_t)(row0 + row) * K + c8 * 8);
            *(uint4*)(sAh + row * LD + c8 * 8) = v;
        }
    } else {
        for (int i = tid; i < 64 * (K / 4); i += 256) {
            int row = i / (K / 4), c4 = i % (K / 4);
            int grow = row0 + row;
            float4 v = (grow < n) ? *(const float4*)(Ain + (size_t)grow * K + c4 * 4)
                                  : make_float4(0.f, 0.f, 0.f, 0.f);
            __half hx = __float2half_rn(v.x), hy = __float2half_rn(v.y);
            __half hz = __float2half_rn(v.z), hw = __float2half_rn(v.w);
            __half* ph = sAh + row * LD + c4 * 4;
            ph[0] = hx; ph[1] = hy; ph[2] = hz; ph[3] = hw;
            __half* pl = sAl + row * LD + c4 * 4;
            pl[0] = __float2half_rn(v.x - __half2float(hx));
            pl[1] = __float2half_rn(v.y - __half2float(hy));
            pl[2] = __float2half_rn(v.z - __half2float(hz));
            pl[3] = __float2half_rn(v.w - __half2float(hw));
        }
    }
    __syncthreads();

    float acc[4][4];
#pragma unroll
    for (int f = 0; f < 4; f++)
#pragma unroll
        for (int j = 0; j < 4; j++) acc[f][j] = 0.f;

    int g = lane >> 2, t = lane & 3;

#pragma unroll
    for (int ks = 0; ks < K / 16; ks++) {
        int kk = ks * 16 + t * 2;
        int r = wm * 16 + g;
        unsigned ah[4], al[4];
        ah[0] = *(const unsigned*)(sAh + r * LD + kk);
        ah[1] = *(const unsigned*)(sAh + (r + 8) * LD + kk);
        ah[2] = *(const unsigned*)(sAh + r * LD + kk + 8);
        ah[3] = *(const unsigned*)(sAh + (r + 8) * LD + kk + 8);
        if (!HALF_IN) {
            al[0] = *(const unsigned*)(sAl + r * LD + kk);
            al[1] = *(const unsigned*)(sAl + (r + 8) * LD + kk);
            al[2] = *(const unsigned*)(sAl + r * LD + kk + 8);
            al[3] = *(const unsigned*)(sAl + (r + 8) * LD + kk + 8);
        }
#pragma unroll
        for (int nf = 0; nf < 4; nf++) {
            int nn = wn * 32 + nf * 8 + g;
            unsigned bh[2], bl[2];
            bh[0] = *(const unsigned*)(sWh + nn * LD + kk);
            bh[1] = *(const unsigned*)(sWh + nn * LD + kk + 8);
            bl[0] = *(const unsigned*)(sWl + nn * LD + kk);
            bl[1] = *(const unsigned*)(sWl + nn * LD + kk + 8);
            mma16816(acc[nf], ah, bh);
            mma16816(acc[nf], ah, bl);
            if (!HALF_IN) mma16816(acc[nf], al, bh);
        }
    }

    // epilogue: scale by dis[row], store fp16
    int r0 = row0 + wm * 16 + g, r1 = r0 + 8;
    float d0 = (r0 < n) ? g_dis[r0] : 0.f;
    float d1 = (r1 < n) ? g_dis[r1] : 0.f;
#pragma unroll
    for (int nf = 0; nf < 4; nf++) {
        int col = wn * 32 + nf * 8 + t * 2;
        if (r0 < n)
            *(__half2*)(g_h + (size_t)r0 * 64 + col) =
                __floats2half2_rn(acc[nf][0] * d0, acc[nf][1] * d0);
        if (r1 < n)
            *(__half2*)(g_h + (size_t)r1 * 64 + col) =
                __floats2half2_rn(acc[nf][2] * d1, acc[nf][3] * d1);
    }
}

// ---------------- aggregation: warp per dst node (R2 body) ------------------
// out[i] = relu( dis[i] * (h'[i] + sum_{src in nbrs} h'[src]) + bias )
// h' rows are fp16 (128B/row, one half2 per lane). Accumulate fp32.
// FC=true additionally applies the 64->4 FC + bfc and writes float4 per node.
template <bool FC>
__global__ void __launch_bounds__(256) k_agg(const float* __restrict__ bias,
                                             const float* __restrict__ Wfc,
                                             const float* __restrict__ bfc,
                                             float* __restrict__ out, int n) {
    int w = (blockIdx.x * 256 + threadIdx.x) >> 5;
    int lane = threadIdx.x & 31;
    if (w >= n) return;

    int start = w ? (__ldg(&g_rptr[w - 1]) + __ldg(&g_bsum[(w - 1) >> 10])) : 0;
    int end = __ldg(&g_rptr[w]) + __ldg(&g_bsum[w >> 10]);

    const __half2* __restrict__ H2 = (const __half2*)g_h;
    float2 acc = __half22float2(H2[(size_t)w * 32 + lane]);   // self loop

    int e = start;
    for (; e + 4 <= end; e += 4) {
        int s0 = __ldg(&g_col[e]), s1 = __ldg(&g_col[e + 1]);
        int s2 = __ldg(&g_col[e + 2]), s3 = __ldg(&g_col[e + 3]);
        float2 v0 = __half22float2(H2[(size_t)s0 * 32 + lane]);
        float2 v1 = __half22float2(H2[(size_t)s1 * 32 + lane]);
        float2 v2 = __half22float2(H2[(size_t)s2 * 32 + lane]);
        float2 v3 = __half22float2(H2[(size_t)s3 * 32 + lane]);
        acc.x += (v0.x + v1.x) + (v2.x + v3.x);
        acc.y += (v0.y + v1.y) + (v2.y + v3.y);
    }
    for (; e < end; e++) {
        float2 v = __half22float2(H2[(size_t)__ldg(&g_col[e]) * 32 + lane]);
        acc.x += v.x;
        acc.y += v.y;
    }

    float d = g_dis[w];
    float2 b = ((const float2*)bias)[lane];
    float ox = fmaxf(fmaf(acc.x, d, b.x), 0.f);
    float oy = fmaxf(fmaf(acc.y, d, b.y), 0.f);

    if (!FC) {
        ((__half2*)g_a)[(size_t)w * 32 + lane] = __floats2half2_rn(ox, oy);
    } else {
        const float4* Wf = (const float4*)Wfc;   // [64][4]
        float4 w0 = Wf[2 * lane], w1 = Wf[2 * lane + 1];
        float4 y;
        y.x = ox * w0.x + oy * w1.x;
        y.y = ox * w0.y + oy * w1.y;
        y.z = ox * w0.z + oy * w1.z;
        y.w = ox * w0.w + oy * w1.w;
#pragma unroll
        for (int o = 16; o; o >>= 1) {
            y.x += __shfl_xor_sync(0xffffffffu, y.x, o);
            y.y += __shfl_xor_sync(0xffffffffu, y.y, o);
            y.z += __shfl_xor_sync(0xffffffffu, y.z, o);
            y.w += __shfl_xor_sync(0xffffffffu, y.w, o);
        }
        if (lane == 0) {
            float4 bf = *(const float4*)bfc;
            ((float4*)out)[w] = make_float4(y.x + bf.x, y.y + bf.y, y.z + bf.z, y.w + bf.w);
        }
    }
}

// ---------------- launch ----------------------------------------------------

extern "C" void kernel_launch(void* const* d_in, const int* in_sizes, int n_in,
                              void* d_out, int out_size) {
    const float* x   = (const float*)d_in[0];
    const int*   ei  = (const int*)d_in[1];
    const float* W1  = (const float*)d_in[2];
    const float* b1  = (const float*)d_in[3];
    const float* W2  = (const float*)d_in[4];
    const float* b2  = (const float*)d_in[5];
    const float* Wfc = (const float*)d_in[6];
    const float* bfc = (const float*)d_in[7];

    int n = in_sizes[0] / 128;
    int E = in_sizes[1] / 2;
    if (n > NMAX) n = NMAX;
    if (E > ECAP) E = ECAP;
    const int* src = ei;
    const int* dst = ei + E;
    int nb = (n + 1023) / 1024;
    int e4b = (E / 4 + 256) / 256;

    // smem: layer1 = 4 planes of 64*(128+8) halves; layer2 = 3 planes of 64*(64+8)
    const int SM1 = 4 * 64 * (128 + 8) * 2;   // 69632
    const int SM2 = 3 * 64 * (64 + 8) * 2;    // 27648
    cudaFuncSetAttribute(k_gemm_mma<128, false>,
                         cudaFuncAttributeMaxDynamicSharedMemorySize, SM1);
    cudaFuncSetAttribute(k_gemm_mma<64, true>,
                         cudaFuncAttributeMaxDynamicSharedMemorySize, SM2);

    // one-time side stream + events (resource init only; no per-call work change)
    static cudaStream_t sB = nullptr;
    static cudaEvent_t evFork = nullptr, evJoin = nullptr;
    if (!sB) {
        cudaStreamCreateWithFlags(&sB, cudaStreamNonBlocking);
        cudaEventCreateWithFlags(&evFork, cudaEventDisableTiming);
        cudaEventCreateWithFlags(&evJoin, cudaEventDisableTiming);
    }

    void* cnt_ptr = nullptr;
    cudaGetSymbolAddress(&cnt_ptr, g_cnt);
    cudaMemsetAsync(cnt_ptr, 0, (size_t)n * sizeof(int));

    k_hist<<<e4b, 256>>>(dst, E);
    k_scan1<<<nb, 1024>>>(n);

    // fork: gemm1 depends only on scan1 (needs dis); overlaps scan2 + fill,
    // which are latency-bound (issue ~2.5%) and leave the SMs nearly idle.
    cudaEventRecord(evFork, 0);
    cudaStreamWaitEvent(sB, evFork, 0);
    int gb = (n + 63) / 64;
    k_gemm_mma<128, false><<<gb, 256, SM1, sB>>>(x, W1, n);
    cudaEventRecord(evJoin, sB);

    k_scan2<<<1, 1024>>>(nb);
    k_fill<<<e4b, 256>>>(src, dst, E);

    cudaStreamWaitEvent(0, evJoin, 0);   // join before agg1 reads g_h

    k_agg<false><<<(n + 7) / 8, 256>>>(b1, nullptr, nullptr, nullptr, n);
    k_gemm_mma<64, true><<<gb, 256, SM2>>>(nullptr, W2, n);
    k_agg<true><<<(n + 7) / 8, 256>>>(b2, Wfc, bfc, (float*)d_out, n);
}

// round 8
// speedup vs baseline: 1.0465x; 1.0465x over previous
#include <cuda_runtime.h>
#include <cuda_fp16.h>

// ---------------- scratch (device globals; no allocation allowed) ----------
#define NMAX  100032
#define ECAP  1664000

__device__ __half g_h [NMAX * 64];   // GEMM output (pre-scaled by dis[row]), fp16
__device__ __half g_a [NMAX * 64];   // post-aggregation activations, fp16
__device__ float  g_dis[NMAX];
__device__ int    g_cnt[NMAX];
__device__ int    g_rptr[NMAX];      // after fill: block-local inclusive prefix
__device__ int    g_col[ECAP];
__device__ int    g_bsum[128];       // exclusive scan of block totals (carry)

// ---------------- preprocessing kernels ------------------------------------

__global__ void k_hist(const int* __restrict__ dst, int E) {
    int e = (blockIdx.x * 256 + threadIdx.x) * 4;
    if (e + 4 <= E) {
        int4 d = *(const int4*)(dst + e);
        atomicAdd(&g_cnt[d.x], 1);
        atomicAdd(&g_cnt[d.y], 1);
        atomicAdd(&g_cnt[d.z], 1);
        atomicAdd(&g_cnt[d.w], 1);
    } else {
        for (; e < E; e++) atomicAdd(&g_cnt[dst[e]], 1);
    }
}

// block-wide exclusive scan helper (blockDim.x == 1024)
__device__ __forceinline__ int blockscan_excl(int v, int* total) {
    __shared__ int ws[32];
    int lane = threadIdx.x & 31, wid = threadIdx.x >> 5;
    int s = v;
#pragma unroll
    for (int o = 1; o < 32; o <<= 1) {
        int t = __shfl_up_sync(0xffffffffu, s, o);
        if (lane >= o) s += t;
    }
    if (lane == 31) ws[wid] = s;
    __syncthreads();
    if (wid == 0) {
        int u = ws[lane];
#pragma unroll
        for (int o = 1; o < 32; o <<= 1) {
            int t = __shfl_up_sync(0xffffffffu, u, o);
            if (lane >= o) u += t;
        }
        ws[lane] = u;
    }
    __syncthreads();
    int incl = s + (wid ? ws[wid - 1] : 0);
    if (total) *total = ws[31];
    return incl - v;
}

// per-block exclusive scan of cnt -> rptr (local), block totals -> bsum,
// fused with dis = rsqrt(deg+1)
__global__ void k_scan1(int n) {
    int i = blockIdx.x * 1024 + threadIdx.x;
    int v = (i < n) ? g_cnt[i] : 0;
    int tot;
    int ex = blockscan_excl(v, &tot);
    if (i < n) {
        g_rptr[i] = ex;
        g_dis[i] = rsqrtf((float)(v + 1));   // +1 self loop; always > 0
    }
    if (threadIdx.x == 0) g_bsum[blockIdx.x] = tot;
}

// exclusive scan of block sums (single block)
__global__ void k_scan2(int nb) {
    int i = threadIdx.x;
    int v = (i < nb) ? g_bsum[i] : 0;   // reads complete before writes (barrier in scan)
    int ex = blockscan_excl(v, nullptr);
    if (i < nb) g_bsum[i] = ex;
}

// ---------------- mma.sync helper -------------------------------------------
__device__ __forceinline__ void mma16816(float acc[4], const unsigned a[4],
                                         const unsigned b[2]) {
    asm volatile(
        "mma.sync.aligned.m16n8k16.row.col.f32.f16.f16.f32 "
        "{%0,%1,%2,%3}, {%4,%5,%6,%7}, {%8,%9}, {%0,%1,%2,%3};\n"
        : "+f"(acc[0]), "+f"(acc[1]), "+f"(acc[2]), "+f"(acc[3])
        : "r"(a[0]), "r"(a[1]), "r"(a[2]), "r"(a[3]), "r"(b[0]), "r"(b[1]));
}

__device__ __forceinline__ unsigned pack_hi(float2 f, unsigned& lo) {
    __half hx = __float2half_rn(f.x), hy = __float2half_rn(f.y);
    __half2 l2 = __halves2half2(__float2half_rn(f.x - __half2float(hx)),
                                __float2half_rn(f.y - __half2float(hy)));
    lo = *(unsigned*)&l2;
    __half2 h2 = __halves2half2(hx, hy);
    return *(unsigned*)&h2;
}

// ---------------- FUSED: gemm1 (blocks < gb) + CSR fill (blocks >= gb) ------
// gemm1: H[n,64] = (x[n,128] @ W1) * dis[row] -> fp16 g_h
//   64 rows x 64 cols per block, 8 warps (wm=wid&3 rows, wn=wid>>2 col half).
//   W^T staged hi/lo in smem (34.8 KB); A fragments loaded DIRECTLY from
//   global x and hi/lo-split in registers (each element read once; 256B/warp
//   coalesced). D = Ah*Wh + Ah*Wl + Al*Wh (dropped Al*Wl ~ eps^2).
// fill: slot = local post-increment + block carry (latency-bound atomics).
// The two bodies have disjoint read/write sets; co-residency lets fill's idle
// issue slots absorb the gemm's tensor work.
__global__ void __launch_bounds__(256) k_gemm1_fill(
        const float* __restrict__ Ain, const float* __restrict__ W, int n, int gb,
        const int* __restrict__ src, const int* __restrict__ dst, int E) {
    constexpr int K = 128;
    constexpr int LD = K + 8;
    extern __shared__ __align__(16) char dyn[];

    if (blockIdx.x >= gb) {
        // ---------------- fill body ----------------
        int e = ((blockIdx.x - gb) * 256 + threadIdx.x) * 4;
        if (e + 4 <= E) {
            int4 d = *(const int4*)(dst + e);
            int4 s = *(const int4*)(src + e);
            g_col[atomicAdd(&g_rptr[d.x], 1) + g_bsum[d.x >> 10]] = s.x;
            g_col[atomicAdd(&g_rptr[d.y], 1) + g_bsum[d.y >> 10]] = s.y;
            g_col[atomicAdd(&g_rptr[d.z], 1) + g_bsum[d.z >> 10]] = s.z;
            g_col[atomicAdd(&g_rptr[d.w], 1) + g_bsum[d.w >> 10]] = s.w;
        } else {
            for (; e < E; e++) {
                int d = dst[e];
                g_col[atomicAdd(&g_rptr[d], 1) + g_bsum[d >> 10]] = src[e];
            }
        }
        return;
    }

    // ---------------- gemm1 body ----------------
    __half* sWh = (__half*)dyn;            // [64][LD] W^T hi
    __half* sWl = sWh + 64 * LD;           // [64][LD] W^T lo

    int tid = threadIdx.x;
    int wid = tid >> 5, lane = tid & 31;
    int wm = wid & 3, wn = wid >> 2;
    int row0 = blockIdx.x * 64;

    for (int i = tid; i < K * 64; i += 256) {
        int k = i >> 6, nn = i & 63;
        float w = W[i];
        __half h = __float2half_rn(w);
        sWh[nn * LD + k] = h;
        sWl[nn * LD + k] = __float2half_rn(w - __half2float(h));
    }
    __syncthreads();

    float acc[4][4];
#pragma unroll
    for (int f = 0; f < 4; f++)
#pragma unroll
        for (int j = 0; j < 4; j++) acc[f][j] = 0.f;

    int g = lane >> 2, t = lane & 3;
    int r0 = row0 + wm * 16 + g, r1 = r0 + 8;
    bool ok0 = r0 < n, ok1 = r1 < n;
    const float* A0 = Ain + (size_t)r0 * K;
    const float* A1 = Ain + (size_t)r1 * K;
    const float2 z2 = make_float2(0.f, 0.f);

#pragma unroll
    for (int ks = 0; ks < K / 16; ks++) {
        int kk = ks * 16 + t * 2;
        float2 f0 = ok0 ? *(const float2*)(A0 + kk) : z2;
        float2 f1 = ok1 ? *(const float2*)(A1 + kk) : z2;
        float2 f2 = ok0 ? *(const float2*)(A0 + kk + 8) : z2;
        float2 f3 = ok1 ? *(const float2*)(A1 + kk + 8) : z2;
        unsigned ah[4], al[4];
        ah[0] = pack_hi(f0, al[0]);
        ah[1] = pack_hi(f1, al[1]);
        ah[2] = pack_hi(f2, al[2]);
        ah[3] = pack_hi(f3, al[3]);
#pragma unroll
        for (int nf = 0; nf < 4; nf++) {
            int nn = wn * 32 + nf * 8 + g;
            unsigned bh[2], bl[2];
            bh[0] = *(const unsigned*)(sWh + nn * LD + kk);
            bh[1] = *(const unsigned*)(sWh + nn * LD + kk + 8);
            bl[0] = *(const unsigned*)(sWl + nn * LD + kk);
            bl[1] = *(const unsigned*)(sWl + nn * LD + kk + 8);
            mma16816(acc[nf], ah, bh);
            mma16816(acc[nf], ah, bl);
            mma16816(acc[nf], al, bh);
        }
    }

    float d0 = ok0 ? g_dis[r0] : 0.f;
    float d1 = ok1 ? g_dis[r1] : 0.f;
#pragma unroll
    for (int nf = 0; nf < 4; nf++) {
        int col = wn * 32 + nf * 8 + t * 2;
        if (ok0)
            *(__half2*)(g_h + (size_t)r0 * 64 + col) =
                __floats2half2_rn(acc[nf][0] * d0, acc[nf][1] * d0);
        if (ok1)
            *(__half2*)(g_h + (size_t)r1 * 64 + col) =
                __floats2half2_rn(acc[nf][2] * d1, acc[nf][3] * d1);
    }
}

// ---------------- GEMM2 via mma.sync (R6 proven path) -----------------------
// H[n,64] = (g_a[n,64] @ W2) * dis[row] -> fp16 g_h ; A exact fp16.
__global__ void __launch_bounds__(256) k_gemm2_mma(const float* __restrict__ W, int n) {
    constexpr int K = 64;
    constexpr int LD = K + 8;
    extern __shared__ __align__(16) char dyn[];
    __half* sWh = (__half*)dyn;              // [64][LD]  W^T hi
    __half* sWl = sWh + 64 * LD;             // [64][LD]  W^T lo
    __half* sAh = sWl + 64 * LD;             // [64][LD]  A (exact)

    int tid = threadIdx.x;
    int wid = tid >> 5, lane = tid & 31;
    int wm = wid & 3, wn = wid >> 2;
    int row0 = blockIdx.x * 64;

    for (int i = tid; i < K * 64; i += 256) {
        int k = i >> 6, nn = i & 63;
        float w = W[i];
        __half h = __float2half_rn(w);
        sWh[nn * LD + k] = h;
        sWl[nn * LD + k] = __float2half_rn(w - __half2float(h));
    }
    for (int i = tid; i < 64 * (K / 8); i += 256) {
        int row = i / (K / 8), c8 = i % (K / 8);
        uint4 v = *(const uint4*)(g_a + (size_t)(row0 + row) * K + c8 * 8);
        *(uint4*)(sAh + row * LD + c8 * 8) = v;
    }
    __syncthreads();

    float acc[4][4];
#pragma unroll
    for (int f = 0; f < 4; f++)
#pragma unroll
        for (int j = 0; j < 4; j++) acc[f][j] = 0.f;

    int g = lane >> 2, t = lane & 3;

#pragma unroll
    for (int ks = 0; ks < K / 16; ks++) {
        int kk = ks * 16 + t * 2;
        int r = wm * 16 + g;
        unsigned ah[4];
        ah[0] = *(const unsigned*)(sAh + r * LD + kk);
        ah[1] = *(const unsigned*)(sAh + (r + 8) * LD + kk);
        ah[2] = *(const unsigned*)(sAh + r * LD + kk + 8);
        ah[3] = *(const unsigned*)(sAh + (r + 8) * LD + kk + 8);
#pragma unroll
        for (int nf = 0; nf < 4; nf++) {
            int nn = wn * 32 + nf * 8 + g;
            unsigned bh[2], bl[2];
            bh[0] = *(const unsigned*)(sWh + nn * LD + kk);
            bh[1] = *(const unsigned*)(sWh + nn * LD + kk + 8);
            bl[0] = *(const unsigned*)(sWl + nn * LD + kk);
            bl[1] = *(const unsigned*)(sWl + nn * LD + kk + 8);
            mma16816(acc[nf], ah, bh);
            mma16816(acc[nf], ah, bl);
        }
    }

    int r0 = row0 + wm * 16 + g, r1 = r0 + 8;
    float d0 = (r0 < n) ? g_dis[r0] : 0.f;
    float d1 = (r1 < n) ? g_dis[r1] : 0.f;
#pragma unroll
    for (int nf = 0; nf < 4; nf++) {
        int col = wn * 32 + nf * 8 + t * 2;
        if (r0 < n)
            *(__half2*)(g_h + (size_t)r0 * 64 + col) =
                __floats2half2_rn(acc[nf][0] * d0, acc[nf][1] * d0);
        if (r1 < n)
            *(__half2*)(g_h + (size_t)r1 * 64 + col) =
                __floats2half2_rn(acc[nf][2] * d1, acc[nf][3] * d1);
    }
}

// ---------------- aggregation: warp per dst node (R6 body) ------------------
template <bool FC>
__global__ void __launch_bounds__(256) k_agg(const float* __restrict__ bias,
                                             const float* __restrict__ Wfc,
                                             const float* __restrict__ bfc,
                                             float* __restrict__ out, int n) {
    int w = (blockIdx.x * 256 + threadIdx.x) >> 5;
    int lane = threadIdx.x & 31;
    if (w >= n) return;

    int start = w ? (__ldg(&g_rptr[w - 1]) + __ldg(&g_bsum[(w - 1) >> 10])) : 0;
    int end = __ldg(&g_rptr[w]) + __ldg(&g_bsum[w >> 10]);

    const __half2* __restrict__ H2 = (const __half2*)g_h;
    float2 acc = __half22float2(H2[(size_t)w * 32 + lane]);   // self loop

    int e = start;
    for (; e + 4 <= end; e += 4) {
        int s0 = __ldg(&g_col[e]), s1 = __ldg(&g_col[e + 1]);
        int s2 = __ldg(&g_col[e + 2]), s3 = __ldg(&g_col[e + 3]);
        float2 v0 = __half22float2(H2[(size_t)s0 * 32 + lane]);
        float2 v1 = __half22float2(H2[(size_t)s1 * 32 + lane]);
        float2 v2 = __half22float2(H2[(size_t)s2 * 32 + lane]);
        float2 v3 = __half22float2(H2[(size_t)s3 * 32 + lane]);
        acc.x += (v0.x + v1.x) + (v2.x + v3.x);
        acc.y += (v0.y + v1.y) + (v2.y + v3.y);
    }
    for (; e < end; e++) {
        float2 v = __half22float2(H2[(size_t)__ldg(&g_col[e]) * 32 + lane]);
        acc.x += v.x;
        acc.y += v.y;
    }

    float d = g_dis[w];
    float2 b = ((const float2*)bias)[lane];
    float ox = fmaxf(fmaf(acc.x, d, b.x), 0.f);
    float oy = fmaxf(fmaf(acc.y, d, b.y), 0.f);

    if (!FC) {
        ((__half2*)g_a)[(size_t)w * 32 + lane] = __floats2half2_rn(ox, oy);
    } else {
        const float4* Wf = (const float4*)Wfc;   // [64][4]
        float4 w0 = Wf[2 * lane], w1 = Wf[2 * lane + 1];
        float4 y;
        y.x = ox * w0.x + oy * w1.x;
        y.y = ox * w0.y + oy * w1.y;
        y.z = ox * w0.z + oy * w1.z;
        y.w = ox * w0.w + oy * w1.w;
#pragma unroll
        for (int o = 16; o; o >>= 1) {
            y.x += __shfl_xor_sync(0xffffffffu, y.x, o);
            y.y += __shfl_xor_sync(0xffffffffu, y.y, o);
            y.z += __shfl_xor_sync(0xffffffffu, y.z, o);
            y.w += __shfl_xor_sync(0xffffffffu, y.w, o);
        }
        if (lane == 0) {
            float4 bf = *(const float4*)bfc;
            ((float4*)out)[w] = make_float4(y.x + bf.x, y.y + bf.y, y.z + bf.z, y.w + bf.w);
        }
    }
}

// ---------------- launch ----------------------------------------------------

extern "C" void kernel_launch(void* const* d_in, const int* in_sizes, int n_in,
                              void* d_out, int out_size) {
    const float* x   = (const float*)d_in[0];
    const int*   ei  = (const int*)d_in[1];
    const float* W1  = (const float*)d_in[2];
    const float* b1  = (const float*)d_in[3];
    const float* W2  = (const float*)d_in[4];
    const float* b2  = (const float*)d_in[5];
    const float* Wfc = (const float*)d_in[6];
    const float* bfc = (const float*)d_in[7];

    int n = in_sizes[0] / 128;
    int E = in_sizes[1] / 2;
    if (n > NMAX) n = NMAX;
    if (E > ECAP) E = ECAP;
    const int* src = ei;
    const int* dst = ei + E;
    int nb = (n + 1023) / 1024;
    int e4b = (E / 4 + 256) / 256;
    int gb = (n + 63) / 64;

    const int SMF = 2 * 64 * (128 + 8) * 2;   // 34816: W^T hi/lo only
    const int SM2 = 3 * 64 * (64 + 8) * 2;    // 27648
    cudaFuncSetAttribute(k_gemm1_fill,
                         cudaFuncAttributeMaxDynamicSharedMemorySize, SMF);
    cudaFuncSetAttribute(k_gemm2_mma,
                         cudaFuncAttributeMaxDynamicSharedMemorySize, SM2);

    void* cnt_ptr = nullptr;
    cudaGetSymbolAddress(&cnt_ptr, g_cnt);
    cudaMemsetAsync(cnt_ptr, 0, (size_t)n * sizeof(int));

    k_hist<<<e4b, 256>>>(dst, E);
    k_scan1<<<nb, 1024>>>(n);
    k_scan2<<<1, 1024>>>(nb);

    // fused: gemm1 (blocks < gb) + CSR fill (blocks >= gb), single launch
    k_gemm1_fill<<<gb + e4b, 256, SMF>>>(x, W1, n, gb, src, dst, E);

    k_agg<false><<<(n + 7) / 8, 256>>>(b1, nullptr, nullptr, nullptr, n);
    k_gemm2_mma<<<gb, 256, SM2>>>(W2, n);
    k_agg<true><<<(n + 7) / 8, 256>>>(b2, Wfc, bfc, (float*)d_out, n);
}

// round 10
// speedup vs baseline: 1.1575x; 1.1061x over previous
#include <cuda_runtime.h>
#include <cuda_fp16.h>

// ---------------- scratch (device globals; no allocation allowed) ----------
#define NMAX  100032
#define ECAP  1664000

__device__ __half g_h [NMAX * 64];   // GEMM output (pre-scaled by dis[row]), fp16
__device__ __half g_a [NMAX * 64];   // post-aggregation activations, fp16
__device__ float  g_dis[NMAX];
__device__ int    g_cnt[NMAX];
__device__ int    g_rptr[NMAX];      // after fill: block-local inclusive prefix
__device__ int    g_col[ECAP];
__device__ int    g_bsum[128];       // exclusive scan of block totals (carry)

// ---------------- preprocessing kernels ------------------------------------

__global__ void k_hist(const int* __restrict__ dst, int E) {
    int e = (blockIdx.x * 256 + threadIdx.x) * 4;
    if (e + 4 <= E) {
        int4 d = *(const int4*)(dst + e);
        atomicAdd(&g_cnt[d.x], 1);
        atomicAdd(&g_cnt[d.y], 1);
        atomicAdd(&g_cnt[d.z], 1);
        atomicAdd(&g_cnt[d.w], 1);
    } else {
        for (; e < E; e++) atomicAdd(&g_cnt[dst[e]], 1);
    }
}

// block-wide exclusive scan helper (blockDim.x == 1024)
__device__ __forceinline__ int blockscan_excl(int v, int* total) {
    __shared__ int ws[32];
    int lane = threadIdx.x & 31, wid = threadIdx.x >> 5;
    int s = v;
#pragma unroll
    for (int o = 1; o < 32; o <<= 1) {
        int t = __shfl_up_sync(0xffffffffu, s, o);
        if (lane >= o) s += t;
    }
    if (lane == 31) ws[wid] = s;
    __syncthreads();
    if (wid == 0) {
        int u = ws[lane];
#pragma unroll
        for (int o = 1; o < 32; o <<= 1) {
            int t = __shfl_up_sync(0xffffffffu, u, o);
            if (lane >= o) u += t;
        }
        ws[lane] = u;
    }
    __syncthreads();
    int incl = s + (wid ? ws[wid - 1] : 0);
    if (total) *total = ws[31];
    return incl - v;
}

// per-block exclusive scan of cnt -> rptr (local), block totals -> bsum,
// fused with dis = rsqrt(deg+1)
__global__ void k_scan1(int n) {
    int i = blockIdx.x * 1024 + threadIdx.x;
    int v = (i < n) ? g_cnt[i] : 0;
    int tot;
    int ex = blockscan_excl(v, &tot);
    if (i < n) {
        g_rptr[i] = ex;
        g_dis[i] = rsqrtf((float)(v + 1));   // +1 self loop; always > 0
    }
    if (threadIdx.x == 0) g_bsum[blockIdx.x] = tot;
}

// exclusive scan of block sums (single block)
__global__ void k_scan2(int nb) {
    int i = threadIdx.x;
    int v = (i < nb) ? g_bsum[i] : 0;   // reads complete before writes (barrier in scan)
    int ex = blockscan_excl(v, nullptr);
    if (i < nb) g_bsum[i] = ex;
}

// ---------------- mma.sync helpers ------------------------------------------
__device__ __forceinline__ void mma16816(float acc[4], const unsigned a[4],
                                         const unsigned b[2]) {
    asm volatile(
        "mma.sync.aligned.m16n8k16.row.col.f32.f16.f16.f32 "
        "{%0,%1,%2,%3}, {%4,%5,%6,%7}, {%8,%9}, {%0,%1,%2,%3};\n"
        : "+f"(acc[0]), "+f"(acc[1]), "+f"(acc[2]), "+f"(acc[3])
        : "r"(a[0]), "r"(a[1]), "r"(a[2]), "r"(a[3]), "r"(b[0]), "r"(b[1]));
}

__device__ __forceinline__ unsigned pack_hi(float2 f, unsigned& lo) {
    __half hx = __float2half_rn(f.x), hy = __float2half_rn(f.y);
    __half2 l2 = __halves2half2(__float2half_rn(f.x - __half2float(hx)),
                                __float2half_rn(f.y - __half2float(hy)));
    lo = *(unsigned*)&l2;
    __half2 h2 = __halves2half2(hx, hy);
    return *(unsigned*)&h2;
}

// Stage W[K][64] (row-major fp32) into per-thread B-fragment records:
//   sB[(ks*64 + nn)*4 + t] = {bh0, bh1, bl0, bl1}
// where bh0 = hi(W[k0][nn], W[k0+1][nn]), bh1 = hi(W[k0+8][nn], W[k0+9][nn]),
// k0 = ks*16 + t*2; bl* = fp16 residuals. One conflict-free LDS.128 per
// n-fragment in the mainloop replaces four LDS.32.
// NOTE: decomposition of i MUST match the consumer index (ks*64+nn)*4 + t:
//   t = i & 3, nn = (i >> 2) & 63, ks = i >> 8.   (R9 bug: wrong decomposition)
template <int K>
__device__ __forceinline__ void stage_B(uint4* sB, const float* __restrict__ W,
                                        int tid) {
    constexpr int ENT = (K / 16) * 64 * 4;
    for (int i = tid; i < ENT; i += 256) {
        int t = i & 3;
        int nn = (i >> 2) & 63;
        int ks = i >> 8;
        int k0 = ks * 16 + t * 2;
        float w0 = W[k0 * 64 + nn],       w1 = W[(k0 + 1) * 64 + nn];
        float w2 = W[(k0 + 8) * 64 + nn], w3 = W[(k0 + 9) * 64 + nn];
        unsigned l01, l23;
        uint4 v;
        v.x = pack_hi(make_float2(w0, w1), l01);
        v.y = pack_hi(make_float2(w2, w3), l23);
        v.z = l01;
        v.w = l23;
        sB[i] = v;
    }
}

// ---------------- FUSED: gemm1 + CSR fill, role-interleaved ------------------
// Roles alternate with blockIdx over the paired prefix so every scheduling
// wave holds both kinds: fill (L2-atomic latency, issue ~2.5%) co-resident
// with gemm (tensor pipe) lets fill's idle slots absorb the MMA work.
// gemm1: H[n,64] = (x[n,128] @ W1) * dis[row] -> fp16 g_h; A fragments loaded
// directly from global x, hi/lo split in registers (D = Ah*Wh+Ah*Wl+Al*Wh).
__global__ void __launch_bounds__(256) k_gemm1_fill(
        const float* __restrict__ Ain, const float* __restrict__ W, int n, int gb,
        const int* __restrict__ src, const int* __restrict__ dst, int E, int e4b) {
    constexpr int K = 128;
    extern __shared__ __align__(16) uint4 sB[];   // [(K/16)*64*4] = 32 KB

    int mn = (gb < e4b) ? gb : e4b;
    int m2 = 2 * mn;
    bool isFill;
    int id;
    if ((int)blockIdx.x < m2) {
        isFill = (blockIdx.x & 1) == 0;
        id = blockIdx.x >> 1;
    } else {
        int rem = blockIdx.x - m2;
        isFill = (e4b > gb);
        id = mn + rem;
    }

    if (isFill) {
        // ---------------- fill body ----------------
        int e = (id * 256 + threadIdx.x) * 4;
        if (e + 4 <= E) {
            int4 d = *(const int4*)(dst + e);
            int4 s = *(const int4*)(src + e);
            g_col[atomicAdd(&g_rptr[d.x], 1) + g_bsum[d.x >> 10]] = s.x;
            g_col[atomicAdd(&g_rptr[d.y], 1) + g_bsum[d.y >> 10]] = s.y;
            g_col[atomicAdd(&g_rptr[d.z], 1) + g_bsum[d.z >> 10]] = s.z;
            g_col[atomicAdd(&g_rptr[d.w], 1) + g_bsum[d.w >> 10]] = s.w;
        } else {
            for (; e < E; e++) {
                int d = dst[e];
                g_col[atomicAdd(&g_rptr[d], 1) + g_bsum[d >> 10]] = src[e];
            }
        }
        return;
    }

    // ---------------- gemm1 body ----------------
    int tid = threadIdx.x;
    int wid = tid >> 5, lane = tid & 31;
    int wm = wid & 3, wn = wid >> 2;
    int row0 = id * 64;

    stage_B<K>(sB, W, tid);
    __syncthreads();

    float acc[4][4];
#pragma unroll
    for (int f = 0; f < 4; f++)
#pragma unroll
        for (int j = 0; j < 4; j++) acc[f][j] = 0.f;

    int g = lane >> 2, t = lane & 3;
    int r0 = row0 + wm * 16 + g, r1 = r0 + 8;
    bool ok0 = r0 < n, ok1 = r1 < n;
    const float* A0 = Ain + (size_t)r0 * K;
    const float* A1 = Ain + (size_t)r1 * K;
    const float2 z2 = make_float2(0.f, 0.f);

#pragma unroll
    for (int ks = 0; ks < K / 16; ks++) {
        int kk = ks * 16 + t * 2;
        float2 f0 = ok0 ? *(const float2*)(A0 + kk) : z2;
        float2 f1 = ok1 ? *(const float2*)(A1 + kk) : z2;
        float2 f2 = ok0 ? *(const float2*)(A0 + kk + 8) : z2;
        float2 f3 = ok1 ? *(const float2*)(A1 + kk + 8) : z2;
        unsigned ah[4], al[4];
        ah[0] = pack_hi(f0, al[0]);
        ah[1] = pack_hi(f1, al[1]);
        ah[2] = pack_hi(f2, al[2]);
        ah[3] = pack_hi(f3, al[3]);
#pragma unroll
        for (int nf = 0; nf < 4; nf++) {
            int nn = wn * 32 + nf * 8 + g;
            uint4 v = sB[(ks * 64 + nn) * 4 + t];
            unsigned bh[2] = {v.x, v.y}, bl[2] = {v.z, v.w};
            mma16816(acc[nf], ah, bh);
            mma16816(acc[nf], ah, bl);
            mma16816(acc[nf], al, bh);
        }
    }

    float d0 = ok0 ? g_dis[r0] : 0.f;
    float d1 = ok1 ? g_dis[r1] : 0.f;
#pragma unroll
    for (int nf = 0; nf < 4; nf++) {
        int col = wn * 32 + nf * 8 + t * 2;
        if (ok0)
            *(__half2*)(g_h + (size_t)r0 * 64 + col) =
                __floats2half2_rn(acc[nf][0] * d0, acc[nf][1] * d0);
        if (ok1)
            *(__half2*)(g_h + (size_t)r1 * 64 + col) =
                __floats2half2_rn(acc[nf][2] * d1, acc[nf][3] * d1);
    }
}

// ---------------- GEMM2 via mma.sync ----------------------------------------
// H[n,64] = (g_a[n,64] @ W2) * dis[row] -> fp16 g_h ; A exact fp16 from smem.
__global__ void __launch_bounds__(256) k_gemm2_mma(const float* __restrict__ W, int n) {
    constexpr int K = 64;
    constexpr int LD = K + 8;
    extern __shared__ __align__(16) uint4 dynu[];
    uint4* sB = dynu;                                   // [(K/16)*64*4] = 16 KB
    __half* sAh = (__half*)(dynu + (K / 16) * 64 * 4);  // [64][LD]

    int tid = threadIdx.x;
    int wid = tid >> 5, lane = tid & 31;
    int wm = wid & 3, wn = wid >> 2;
    int row0 = blockIdx.x * 64;

    stage_B<K>(sB, W, tid);
    for (int i = tid; i < 64 * (K / 8); i += 256) {
        int row = i / (K / 8), c8 = i % (K / 8);
        uint4 v = *(const uint4*)(g_a + (size_t)(row0 + row) * K + c8 * 8);
        *(uint4*)(sAh + row * LD + c8 * 8) = v;
    }
    __syncthreads();

    float acc[4][4];
#pragma unroll
    for (int f = 0; f < 4; f++)
#pragma unroll
        for (int j = 0; j < 4; j++) acc[f][j] = 0.f;

    int g = lane >> 2, t = lane & 3;

#pragma unroll
    for (int ks = 0; ks < K / 16; ks++) {
        int kk = ks * 16 + t * 2;
        int r = wm * 16 + g;
        unsigned ah[4];
        ah[0] = *(const unsigned*)(sAh + r * LD + kk);
        ah[1] = *(const unsigned*)(sAh + (r + 8) * LD + kk);
        ah[2] = *(const unsigned*)(sAh + r * LD + kk + 8);
        ah[3] = *(const unsigned*)(sAh + (r + 8) * LD + kk + 8);
#pragma unroll
        for (int nf = 0; nf < 4; nf++) {
            int nn = wn * 32 + nf * 8 + g;
            uint4 v = sB[(ks * 64 + nn) * 4 + t];
            unsigned bh[2] = {v.x, v.y}, bl[2] = {v.z, v.w};
            mma16816(acc[nf], ah, bh);
            mma16816(acc[nf], ah, bl);
        }
    }

    int r0 = row0 + wm * 16 + g, r1 = r0 + 8;
    float d0 = (r0 < n) ? g_dis[r0] : 0.f;
    float d1 = (r1 < n) ? g_dis[r1] : 0.f;
#pragma unroll
    for (int nf = 0; nf < 4; nf++) {
        int col = wn * 32 + nf * 8 + t * 2;
        if (r0 < n)
            *(__half2*)(g_h + (size_t)r0 * 64 + col) =
                __floats2half2_rn(acc[nf][0] * d0, acc[nf][1] * d0);
        if (r1 < n)
            *(__half2*)(g_h + (size_t)r1 * 64 + col) =
                __floats2half2_rn(acc[nf][2] * d1, acc[nf][3] * d1);
    }
}

// ---------------- aggregation: warp per dst node ----------------------------
template <bool FC>
__global__ void __launch_bounds__(256) k_agg(const float* __restrict__ bias,
                                             const float* __restrict__ Wfc,
                                             const float* __restrict__ bfc,
                                             float* __restrict__ out, int n) {
    int w = (blockIdx.x * 256 + threadIdx.x) >> 5;
    int lane = threadIdx.x & 31;
    if (w >= n) return;

    int start = w ? (__ldg(&g_rptr[w - 1]) + __ldg(&g_bsum[(w - 1) >> 10])) : 0;
    int end = __ldg(&g_rptr[w]) + __ldg(&g_bsum[w >> 10]);

    const __half2* __restrict__ H2 = (const __half2*)g_h;
    float2 acc = __half22float2(H2[(size_t)w * 32 + lane]);   // self loop

    int e = start;
    for (; e + 4 <= end; e += 4) {
        int s0 = __ldg(&g_col[e]), s1 = __ldg(&g_col[e + 1]);
        int s2 = __ldg(&g_col[e + 2]), s3 = __ldg(&g_col[e + 3]);
        float2 v0 = __half22float2(H2[(size_t)s0 * 32 + lane]);
        float2 v1 = __half22float2(H2[(size_t)s1 * 32 + lane]);
        float2 v2 = __half22float2(H2[(size_t)s2 * 32 + lane]);
        float2 v3 = __half22float2(H2[(size_t)s3 * 32 + lane]);
        acc.x += (v0.x + v1.x) + (v2.x + v3.x);
        acc.y += (v0.y + v1.y) + (v2.y + v3.y);
    }
    for (; e < end; e++) {
        float2 v = __half22float2(H2[(size_t)__ldg(&g_col[e]) * 32 + lane]);
        acc.x += v.x;
        acc.y += v.y;
    }

    float d = g_dis[w];
    float2 b = ((const float2*)bias)[lane];
    float ox = fmaxf(fmaf(acc.x, d, b.x), 0.f);
    float oy = fmaxf(fmaf(acc.y, d, b.y), 0.f);

    if (!FC) {
        ((__half2*)g_a)[(size_t)w * 32 + lane] = __floats2half2_rn(ox, oy);
    } else {
        const float4* Wf = (const float4*)Wfc;   // [64][4]
        float4 w0 = Wf[2 * lane], w1 = Wf[2 * lane + 1];
        float4 y;
        y.x = ox * w0.x + oy * w1.x;
        y.y = ox * w0.y + oy * w1.y;
        y.z = ox * w0.z + oy * w1.z;
        y.w = ox * w0.w + oy * w1.w;
#pragma unroll
        for (int o = 16; o; o >>= 1) {
            y.x += __shfl_xor_sync(0xffffffffu, y.x, o);
            y.y += __shfl_xor_sync(0xffffffffu, y.y, o);
            y.z += __shfl_xor_sync(0xffffffffu, y.z, o);
            y.w += __shfl_xor_sync(0xffffffffu, y.w, o);
        }
        if (lane == 0) {
            float4 bf = *(const float4*)bfc;
            ((float4*)out)[w] = make_float4(y.x + bf.x, y.y + bf.y, y.z + bf.z, y.w + bf.w);
        }
    }
}

// ---------------- launch ----------------------------------------------------

extern "C" void kernel_launch(void* const* d_in, const int* in_sizes, int n_in,
                              void* d_out, int out_size) {
    const float* x   = (const float*)d_in[0];
    const int*   ei  = (const int*)d_in[1];
    const float* W1  = (const float*)d_in[2];
    const float* b1  = (const float*)d_in[3];
    const float* W2  = (const float*)d_in[4];
    const float* b2  = (const float*)d_in[5];
    const float* Wfc = (const float*)d_in[6];
    const float* bfc = (const float*)d_in[7];

    int n = in_sizes[0] / 128;
    int E = in_sizes[1] / 2;
    if (n > NMAX) n = NMAX;
    if (E > ECAP) E = ECAP;
    const int* src = ei;
    const int* dst = ei + E;
    int nb = (n + 1023) / 1024;
    int e4b = (E / 4 + 256) / 256;
    int gb = (n + 63) / 64;

    const int SMF = (128 / 16) * 64 * 4 * 16;                    // 32768
    const int SM2 = (64 / 16) * 64 * 4 * 16 + 64 * (64 + 8) * 2; // 25600
    cudaFuncSetAttribute(k_gemm1_fill,
                         cudaFuncAttributeMaxDynamicSharedMemorySize, SMF);
    cudaFuncSetAttribute(k_gemm2_mma,
                         cudaFuncAttributeMaxDynamicSharedMemorySize, SM2);

    void* cnt_ptr = nullptr;
    cudaGetSymbolAddress(&cnt_ptr, g_cnt);
    cudaMemsetAsync(cnt_ptr, 0, (size_t)n * sizeof(int));

    k_hist<<<e4b, 256>>>(dst, E);
    k_scan1<<<nb, 1024>>>(n);
    k_scan2<<<1, 1024>>>(nb);

    // fused: gemm1 + CSR fill, roles interleaved across the grid
    k_gemm1_fill<<<gb + e4b, 256, SMF>>>(x, W1, n, gb, src, dst, E, e4b);

    k_agg<false><<<(n + 7) / 8, 256>>>(b1, nullptr, nullptr, nullptr, n);
    k_gemm2_mma<<<gb, 256, SM2>>>(W2, n);
    k_agg<true><<<(n + 7) / 8, 256>>>(b2, Wfc, bfc, (float*)d_out, n);
}